// round 4
// baseline (speedup 1.0000x reference)
#include <cuda_runtime.h>
#include <math.h>

#define NN 50000
#define EE 800000
#define FIN 128
#define HEADS 8
#define HID 32
#define FHID 256          // HEADS*HID
#define CC 40
#define NEG 0.2f

// ---------------- scratch (static device memory; no allocs allowed) --------
__device__ float g_h1[NN * FHID];        // x@W1
__device__ float g_out1[NN * FHID];      // elu(agg1 + b1)
__device__ float g_as1[NN * HEADS];
__device__ float g_ad1[NN * HEADS];
__device__ float g_h2[NN * CC];          // out1@W2
__device__ float g_as2[NN];
__device__ float g_ad2[NN];
__device__ int   g_cnt[NN];              // degree, then scatter cursor
__device__ int   g_rowptr[NN + 1];
__device__ int   g_srci[EE + NN];        // src node per CSR slot (self-loops included)

// ---------------- helpers --------------------------------------------------
__device__ __forceinline__ float wredmax(float v) {
#pragma unroll
    for (int o = 16; o; o >>= 1) v = fmaxf(v, __shfl_xor_sync(0xffffffffu, v, o));
    return v;
}
__device__ __forceinline__ float wredsum(float v) {
#pragma unroll
    for (int o = 16; o; o >>= 1) v += __shfl_xor_sync(0xffffffffu, v, o);
    return v;
}
__device__ __forceinline__ float lrelu(float x) { return x > 0.f ? x : NEG * x; }

// ---------------- CSR build ------------------------------------------------
__global__ void k_init_deg() {
    int v = blockIdx.x * blockDim.x + threadIdx.x;
    if (v < NN) g_cnt[v] = 1;  // self-loop
}

__global__ void k_hist(const int* __restrict__ ei) {
    int e = blockIdx.x * blockDim.x + threadIdx.x;
    if (e < EE) atomicAdd(&g_cnt[ei[EE + e]], 1);
}

__global__ void k_scan() {
    __shared__ int s[1024];
    __shared__ int carry;
    int tid = threadIdx.x;
    if (tid == 0) { carry = 0; g_rowptr[0] = 0; }
    __syncthreads();
    for (int base = 0; base < NN; base += 1024) {
        int i = base + tid;
        int x = (i < NN) ? g_cnt[i] : 0;
        s[tid] = x;
        __syncthreads();
#pragma unroll
        for (int off = 1; off < 1024; off <<= 1) {
            int t = (tid >= off) ? s[tid - off] : 0;
            __syncthreads();
            s[tid] += t;
            __syncthreads();
        }
        if (i < NN) g_rowptr[i + 1] = carry + s[tid];
        __syncthreads();
        if (tid == 0) carry += s[1023];
        __syncthreads();
    }
}

__global__ void k_selfloop() {
    int v = blockIdx.x * blockDim.x + threadIdx.x;
    if (v < NN) {
        int p = g_rowptr[v];
        g_srci[p] = v;
        g_cnt[v] = p + 1;   // cursor past self-loop
    }
}

__global__ void k_scatter(const int* __restrict__ ei) {
    int e = blockIdx.x * blockDim.x + threadIdx.x;
    if (e < EE) {
        int dst = ei[EE + e];
        int src = ei[e];
        int pos = atomicAdd(&g_cnt[dst], 1);
        g_srci[pos] = src;
    }
}

// ---------------- GEMM1: h1 = x @ W1  (50000x128 @ 128x256) ----------------
__global__ void k_gemm1(const float* __restrict__ x, const float* __restrict__ W) {
    __shared__ float As[64 * 16];
    __shared__ float Bs[16 * 64];
    int tid = threadIdx.x;
    int brow = blockIdx.y * 64, bcol = blockIdx.x * 64;
    int ty = tid / 16, tx = tid % 16;
    int ar = tid >> 2, ac = (tid & 3) * 4;
    int br = tid >> 4, bc = (tid & 15) * 4;
    float acc[4][4];
#pragma unroll
    for (int i = 0; i < 4; i++)
#pragma unroll
        for (int j = 0; j < 4; j++) acc[i][j] = 0.f;

    for (int kt = 0; kt < FIN; kt += 16) {
        float4 av = make_float4(0.f, 0.f, 0.f, 0.f);
        int grow = brow + ar;
        if (grow < NN) av = *(const float4*)(x + grow * FIN + kt + ac);
        *(float4*)(As + ar * 16 + ac) = av;
        *(float4*)(Bs + br * 64 + bc) = *(const float4*)(W + (kt + br) * FHID + bcol + bc);
        __syncthreads();
#pragma unroll
        for (int k = 0; k < 16; k++) {
            float a0 = As[(ty * 4 + 0) * 16 + k];
            float a1 = As[(ty * 4 + 1) * 16 + k];
            float a2 = As[(ty * 4 + 2) * 16 + k];
            float a3 = As[(ty * 4 + 3) * 16 + k];
            float4 b = *(float4*)(Bs + k * 64 + tx * 4);
            acc[0][0] += a0 * b.x; acc[0][1] += a0 * b.y; acc[0][2] += a0 * b.z; acc[0][3] += a0 * b.w;
            acc[1][0] += a1 * b.x; acc[1][1] += a1 * b.y; acc[1][2] += a1 * b.z; acc[1][3] += a1 * b.w;
            acc[2][0] += a2 * b.x; acc[2][1] += a2 * b.y; acc[2][2] += a2 * b.z; acc[2][3] += a2 * b.w;
            acc[3][0] += a3 * b.x; acc[3][1] += a3 * b.y; acc[3][2] += a3 * b.z; acc[3][3] += a3 * b.w;
        }
        __syncthreads();
    }
#pragma unroll
    for (int i = 0; i < 4; i++) {
        int row = brow + ty * 4 + i;
        if (row < NN)
            *(float4*)(g_h1 + row * FHID + bcol + tx * 4) =
                make_float4(acc[i][0], acc[i][1], acc[i][2], acc[i][3]);
    }
}

// ---------------- attention logits, layer 1 --------------------------------
__global__ void k_alpha1(const float* __restrict__ a1s, const float* __restrict__ a1d) {
    int n = blockIdx.x;
    int tid = threadIdx.x;          // tid = head*32 + d  (matches [8,32] layout)
    int head = tid >> 5, d = tid & 31;
    float v = g_h1[n * FHID + tid];
    float ps = v * a1s[tid];
    float pd = v * a1d[tid];
    ps = wredsum(ps);
    pd = wredsum(pd);
    if (d == 0) {
        g_as1[n * HEADS + head] = ps;
        g_ad1[n * HEADS + head] = pd;
    }
}

// ---------------- layer-1 segment softmax + aggregation + ELU --------------
__global__ void k_agg1(const float* __restrict__ b1) {
    int v = blockIdx.x;
    int beg = g_rowptr[v], end = g_rowptr[v + 1];
    int deg = end - beg;
    int tid = threadIdx.x, lane = tid & 31, head = tid >> 5;

    __shared__ float smx[HEADS], sinv[HEADS];
    __shared__ int   s_src[32];
    __shared__ float s_w[32 * HEADS];

    float adv = g_ad1[v * HEADS + head];
    // phase 1: per-head max
    float mx = -1e30f;
    for (int i = lane; i < deg; i += 32) {
        float e = lrelu(g_as1[g_srci[beg + i] * HEADS + head] + adv);
        mx = fmaxf(mx, e);
    }
    mx = wredmax(mx);
    // phase 2: per-head sum of exp
    float sm = 0.f;
    for (int i = lane; i < deg; i += 32) {
        float e = lrelu(g_as1[g_srci[beg + i] * HEADS + head] + adv);
        sm += expf(e - mx);
    }
    sm = wredsum(sm);
    if (lane == 0) { smx[head] = mx; sinv[head] = 1.f / (sm + 1e-16f); }
    __syncthreads();

    // phase 3: weighted aggregation, chunked
    float acc = 0.f;
    for (int base = 0; base < deg; base += 32) {
        int cnt = min(32, deg - base);
        int el = tid >> 3, hh = tid & 7;
        if (el < cnt) {
            int s = g_srci[beg + base + el];
            if (hh == 0) s_src[el] = s;
            float e = lrelu(g_as1[s * HEADS + hh] + g_ad1[v * HEADS + hh]);
            s_w[el * HEADS + hh] = expf(e - smx[hh]) * sinv[hh];
        }
        __syncthreads();
        for (int e = 0; e < cnt; e++) {
            float w = s_w[e * HEADS + head];
            acc += g_h1[s_src[e] * FHID + tid] * w;
        }
        __syncthreads();
    }
    float r = acc + b1[tid];
    g_out1[v * FHID + tid] = r > 0.f ? r : expm1f(r);   // ELU
}

// ---------------- GEMM2: h2 = out1 @ W2  (50000x256 @ 256x40) --------------
__global__ void k_gemm2(const float* __restrict__ W2) {
    __shared__ float Ws[FHID * CC];   // 40 KB
    __shared__ float Xs[64 * 17];     // 16-wide k tile, padded
    int tid = threadIdx.x;
    int brow = blockIdx.x * 64;
    for (int i = tid; i < FHID * CC; i += 256) Ws[i] = W2[i];
    int r = tid & 63, cg = tid >> 6;            // 4 col-groups of 10
    int lr = tid >> 2, lc = (tid & 3) * 4;
    float acc[10];
#pragma unroll
    for (int j = 0; j < 10; j++) acc[j] = 0.f;

    for (int kt = 0; kt < FHID; kt += 16) {
        __syncthreads();   // also protects Ws on first iter
        float4 xv = make_float4(0.f, 0.f, 0.f, 0.f);
        int grow = brow + lr;
        if (grow < NN) xv = *(const float4*)(g_out1 + grow * FHID + kt + lc);
        Xs[lr * 17 + lc + 0] = xv.x;
        Xs[lr * 17 + lc + 1] = xv.y;
        Xs[lr * 17 + lc + 2] = xv.z;
        Xs[lr * 17 + lc + 3] = xv.w;
        __syncthreads();
#pragma unroll
        for (int k = 0; k < 16; k++) {
            float x = Xs[r * 17 + k];
            const float* wp = Ws + (kt + k) * CC + cg * 10;
#pragma unroll
            for (int j = 0; j < 10; j++) acc[j] += x * wp[j];
        }
    }
    int row = brow + r;
    if (row < NN) {
#pragma unroll
        for (int j = 0; j < 10; j++) g_h2[row * CC + cg * 10 + j] = acc[j];
    }
}

// ---------------- attention logits, layer 2 --------------------------------
__global__ void k_alpha2(const float* __restrict__ a2s, const float* __restrict__ a2d) {
    int n = blockIdx.x * blockDim.x + threadIdx.x;
    if (n >= NN) return;
    float s = 0.f, d = 0.f;
#pragma unroll
    for (int k = 0; k < CC; k++) {
        float v = g_h2[n * CC + k];
        s += v * a2s[k];
        d += v * a2d[k];
    }
    g_as2[n] = s;
    g_ad2[n] = d;
}

// ---------------- layer-2 segment softmax + aggregation --------------------
__global__ void k_agg2(const float* __restrict__ b2, float* __restrict__ out) {
    int v = blockIdx.x;
    int beg = g_rowptr[v], end = g_rowptr[v + 1];
    int deg = end - beg;
    int tid = threadIdx.x;

    __shared__ float smx, sinvs;
    __shared__ int   s_src[64];
    __shared__ float s_w[64];

    float adv = g_ad2[v];
    if (tid < 32) {
        float mx = -1e30f;
        for (int i = tid; i < deg; i += 32)
            mx = fmaxf(mx, lrelu(g_as2[g_srci[beg + i]] + adv));
        mx = wredmax(mx);
        float sm = 0.f;
        for (int i = tid; i < deg; i += 32)
            sm += expf(lrelu(g_as2[g_srci[beg + i]] + adv) - mx);
        sm = wredsum(sm);
        if (tid == 0) { smx = mx; sinvs = 1.f / (sm + 1e-16f); }
    }
    __syncthreads();
    float mx = smx, inv = sinvs;
    float acc = 0.f;
    for (int base = 0; base < deg; base += 64) {
        int cnt = min(64, deg - base);
        if (tid < cnt) {
            int s = g_srci[beg + base + tid];
            s_src[tid] = s;
            float e = lrelu(g_as2[s] + adv);
            s_w[tid] = expf(e - mx) * inv;
        }
        __syncthreads();
        if (tid < CC) {
            for (int e = 0; e < cnt; e++)
                acc += g_h2[s_src[e] * CC + tid] * s_w[e];
        }
        __syncthreads();
    }
    if (tid < CC) out[v * CC + tid] = acc + b2[tid];
}

// ---------------- launch ---------------------------------------------------
extern "C" void kernel_launch(void* const* d_in, const int* in_sizes, int n_in,
                              void* d_out, int out_size) {
    const float* x   = (const float*)d_in[0];
    const int*   ei  = (const int*)d_in[1];      // int32 edge_index [2, E]
    const float* W1  = (const float*)d_in[2];
    const float* a1s = (const float*)d_in[3];
    const float* a1d = (const float*)d_in[4];
    const float* b1  = (const float*)d_in[5];
    const float* W2  = (const float*)d_in[6];
    const float* a2s = (const float*)d_in[7];
    const float* a2d = (const float*)d_in[8];
    const float* b2  = (const float*)d_in[9];
    float*       out = (float*)d_out;

    // CSR build (dst-grouped, self-loops first)
    k_init_deg<<<(NN + 255) / 256, 256>>>();
    k_hist<<<(EE + 255) / 256, 256>>>(ei);
    k_scan<<<1, 1024>>>();
    k_selfloop<<<(NN + 255) / 256, 256>>>();
    k_scatter<<<(EE + 255) / 256, 256>>>(ei);

    // layer 1
    dim3 g1(FHID / 64, (NN + 63) / 64);
    k_gemm1<<<g1, 256>>>(x, W1);
    k_alpha1<<<NN, 256>>>(a1s, a1d);
    k_agg1<<<NN, 256>>>(b1);

    // layer 2
    k_gemm2<<<(NN + 63) / 64, 256>>>(W2);
    k_alpha2<<<(NN + 255) / 256, 256>>>(a2s, a2d);
    k_agg2<<<NN, 64>>>(b2, out);
}